// round 13
// baseline (speedup 1.0000x reference)
#include <cuda_runtime.h>
#include <cstdint>

#define NN 65536
#define KK 6
#define MM 688
#define MQ 172               // float4 per row
#define ROW_BYTES 2752       // MM*4
#define NODE_BYTES 16512     // KK*ROW_BYTES
#define STAGES 6             // per-CTA; multiple of NGROUPS
#define NBLK 1184            // 4 waves of (148 SMs x 2 CTAs) -- tail hiding
#define NGROUPS 2
#define NCONS_G 192          // consumers per group (6 warps, 172 active)
#define NPROD_WARPS 2        // one producer warp per group
#define CONS_BASE (NPROD_WARPS * 32)          // 64
#define NTH (CONS_BASE + NGROUPS * NCONS_G)   // 448
#define MAXNPB 64            // ceil(65536/1184)=56, padded

#define OFF_MBAR 0                         // 6 stages * (full,empty) * 8B = 96 -> pad 128
#define OFF_CNT 128
#define OFF_BUF (OFF_CNT + MAXNPB * 4)     // 384 (16B aligned)
#define SMEM_BYTES (OFF_BUF + STAGES * NODE_BYTES)  // 99456 -> 2 CTAs/SM

extern __shared__ char smem[];

__device__ __forceinline__ uint32_t s2u(const void* p) {
    return (uint32_t)__cvta_generic_to_shared(p);
}

__device__ __forceinline__ void mbar_init(uint32_t mbar, uint32_t count) {
    asm volatile("mbarrier.init.shared.b64 [%0], %1;" :: "r"(mbar), "r"(count) : "memory");
}

__device__ __forceinline__ void mbar_expect_tx(uint32_t mbar, uint32_t bytes) {
    asm volatile("mbarrier.arrive.expect_tx.shared.b64 _, [%0], %1;"
                 :: "r"(mbar), "r"(bytes) : "memory");
}

__device__ __forceinline__ void mbar_arrive(uint32_t mbar) {
    asm volatile("mbarrier.arrive.shared.b64 _, [%0];" :: "r"(mbar) : "memory");
}

__device__ __forceinline__ void mbar_wait(uint32_t mbar, uint32_t parity) {
    asm volatile(
        "{\n\t"
        ".reg .pred P;\n\t"
        "WAIT_%=:\n\t"
        "mbarrier.try_wait.parity.acquire.cta.shared::cta.b64 P, [%0], %1, 0x989680;\n\t"
        "@!P bra WAIT_%=;\n\t"
        "}"
        :: "r"(mbar), "r"(parity) : "memory");
}

__device__ __forceinline__ void bulk_copy(uint32_t dst_smem, const void* src_gmem,
                                          uint32_t bytes, uint32_t mbar) {
    asm volatile(
        "cp.async.bulk.shared::cluster.global.mbarrier::complete_tx::bytes "
        "[%0], [%1], %2, [%3];"
        :: "r"(dst_smem), "l"(src_gmem), "r"(bytes), "r"(mbar) : "memory");
}

__global__ void __launch_bounds__(NTH, 2)
mlp_msg_agg_pipe(
    const char*  __restrict__ msgs,    // [N,K,M] f32 as bytes
    const int*   __restrict__ counts,  // [N]
    const float* __restrict__ ts,      // [N]
    const float* __restrict__ W1, const float* __restrict__ b1,
    const float* __restrict__ W2, const float* __restrict__ b2,
    const float* __restrict__ W3, const float* __restrict__ b3,
    float4*      __restrict__ out,     // [N, MQ]
    float*       __restrict__ out_ts)  // [N] or null
{
    const int tid = threadIdx.x;
    const int blk = blockIdx.x;
    const int start = (int)(((long long)blk * NN) / NBLK);
    const int end   = (int)(((long long)(blk + 1) * NN) / NBLK);
    const int nnode = end - start;     // 55 or 56

    int* s_cnt = (int*)(smem + OFF_CNT);
    const uint32_t mb = s2u(smem + OFF_MBAR);   // full(s)=mb+s*16, empty(s)=mb+s*16+8
    char* buf = smem + OFF_BUF;

    // Prologue: stage counts in smem, pass timestamps through (one iteration)
    if (tid < nnode) {
        s_cnt[tid] = counts[start + tid];
        if (out_ts != nullptr) out_ts[start + tid] = ts[start + tid];
    }
    if (tid == 0) {
        #pragma unroll
        for (int s = 0; s < STAGES; s++) {
            mbar_init(mb + s * 16, 1);            // full: 1 expect_tx arrival
            mbar_init(mb + s * 16 + 8, NCONS_G);  // empty: owning group arrives
        }
    }
    __syncthreads();

    if (tid < CONS_BASE) {
        // ------------- producers: 2 warps, 1 active thread each -------------
        // Producer p (lane 0 of warp p) fills exactly group p's nodes
        // (i ≡ p mod 2) whose stages {p, p+2, p+4} it alone owns. Fills of
        // each stage stay strictly sequential by one thread -> parity safe.
        const int p = tid / 32;
        if ((tid & 31) == 0) {
            int s = p;   // stage of node i (cycles p, p+2, p+4)
            int j = 0;   // fill index = i / STAGES
            for (int i = p; i < nnode; i += NGROUPS) {
                int c = s_cnt[i];
                c = (c < 0) ? 0 : ((c > KK) ? KK : c);
                const uint32_t pp = (j & 1) ^ 1;          // first pass free
                mbar_wait(mb + s * 16 + 8, pp);           // wait stage empty
                const uint32_t bytes = (uint32_t)c * ROW_BYTES;
                mbar_expect_tx(mb + s * 16, bytes);
                if (bytes) {
                    const uint32_t dst =
                        s2u(buf + s * NODE_BYTES + (KK - c) * ROW_BYTES);
                    const char* src =
                        msgs + ((size_t)(start + i) * KK + (KK - c)) * ROW_BYTES;
                    bulk_copy(dst, src, bytes, mb + s * 16);
                }
                s += NGROUPS;
                if (s >= STAGES) { s -= STAGES; j++; }
            }
        }
        return;
    }

    // ---------------- consumers: 2 independent groups ----------------
    // Node i -> stage i % 6, group i % 2. 6 % 2 == 0 ⇒ every stage has a
    // fixed owning group; successive fills consumed sequentially by the same
    // threads ⇒ phase-parity protocol safe.
    const int g    = (tid - CONS_BASE) / NCONS_G;
    const int ctid = (tid - CONS_BASE) - g * NCONS_G;   // 0..191; active if < MQ

    float w1[KK * 3];
    #pragma unroll
    for (int i = 0; i < KK * 3; i++) w1[i] = __ldg(W1 + i);
    const float bb1_0 = __ldg(b1 + 0), bb1_1 = __ldg(b1 + 1), bb1_2 = __ldg(b1 + 2);
    const float w2_00 = __ldg(W2 + 0), w2_01 = __ldg(W2 + 1);
    const float w2_10 = __ldg(W2 + 2), w2_11 = __ldg(W2 + 3);
    const float w2_20 = __ldg(W2 + 4), w2_21 = __ldg(W2 + 5);
    const float bb2_0 = __ldg(b2 + 0), bb2_1 = __ldg(b2 + 1);
    const float w3_0  = __ldg(W3 + 0), w3_1  = __ldg(W3 + 1);
    const float bb3   = __ldg(b3 + 0);

    int s = g;   // stage of node i (cycles g, g+2, g+4)
    int j = 0;   // fill index = i / STAGES
    for (int i = g; i < nnode; i += NGROUPS) {
        mbar_wait(mb + s * 16, (uint32_t)(j & 1));   // wait stage full (acquire)

        if (ctid < MQ) {
            int c = s_cnt[i];
            int k0 = KK - c;
            if (k0 < 0) k0 = 0;
            if (k0 > KK) k0 = KK;

            const char* nb = buf + s * NODE_BYTES + ctid * 16;

            float h[4][3];
            #pragma unroll
            for (int l = 0; l < 4; l++) {
                h[l][0] = bb1_0; h[l][1] = bb1_1; h[l][2] = bb1_2;
            }

            #pragma unroll
            for (int k = 0; k < KK; k++) {
                if (k >= k0) {
                    const float4 v = *(const float4*)(nb + k * ROW_BYTES);
                    const float a  = w1[k * 3 + 0];
                    const float bW = w1[k * 3 + 1];
                    const float cW = w1[k * 3 + 2];
                    const float x[4] = {v.x, v.y, v.z, v.w};
                    #pragma unroll
                    for (int l = 0; l < 4; l++) {
                        h[l][0] = fmaf(x[l], a,  h[l][0]);
                        h[l][1] = fmaf(x[l], bW, h[l][1]);
                        h[l][2] = fmaf(x[l], cW, h[l][2]);
                    }
                }
            }

            float res[4];
            #pragma unroll
            for (int l = 0; l < 4; l++) {
                const float a0 = fmaxf(h[l][0], 0.0f);
                const float a1 = fmaxf(h[l][1], 0.0f);
                const float a2 = fmaxf(h[l][2], 0.0f);
                float g0 = bb2_0, g1 = bb2_1;
                g0 = fmaf(a0, w2_00, g0); g1 = fmaf(a0, w2_01, g1);
                g0 = fmaf(a1, w2_10, g0); g1 = fmaf(a1, w2_11, g1);
                g0 = fmaf(a2, w2_20, g0); g1 = fmaf(a2, w2_21, g1);
                g0 = fmaxf(g0, 0.0f);
                g1 = fmaxf(g1, 0.0f);
                res[l] = fmaf(g0, w3_0, fmaf(g1, w3_1, bb3));
            }

            float4 o;
            o.x = res[0]; o.y = res[1]; o.z = res[2]; o.w = res[3];
            out[(size_t)(start + i) * MQ + ctid] = o;
        }

        mbar_arrive(mb + s * 16 + 8);           // release stage to producer

        s += NGROUPS;
        if (s >= STAGES) { s -= STAGES; j++; }
    }
}

extern "C" void kernel_launch(void* const* d_in, const int* in_sizes, int n_in,
                              void* d_out, int out_size)
{
    const char*  msgs   = (const char*) d_in[0];
    const int*   counts = (const int*)  d_in[1];
    const float* ts     = (const float*)d_in[2];
    const float* W1     = (const float*)d_in[3];
    const float* b1     = (const float*)d_in[4];
    const float* W2     = (const float*)d_in[5];
    const float* b2     = (const float*)d_in[6];
    const float* W3     = (const float*)d_in[7];
    const float* b3     = (const float*)d_in[8];

    float* out = (float*)d_out;
    const int write_ts = (out_size >= NN * MM + NN) ? 1 : 0;
    float* out_ts = write_ts ? (out + (size_t)NN * MM) : nullptr;

    cudaFuncSetAttribute(mlp_msg_agg_pipe,
                         cudaFuncAttributeMaxDynamicSharedMemorySize, SMEM_BYTES);

    mlp_msg_agg_pipe<<<NBLK, NTH, SMEM_BYTES>>>(
        msgs, counts, ts, W1, b1, W2, b2, W3, b3,
        (float4*)out, out_ts);
}

// round 14
// speedup vs baseline: 1.0064x; 1.0064x over previous
#include <cuda_runtime.h>
#include <cstdint>

#define NN 65536
#define KK 6
#define MM 688
#define MQ 172               // float4 per row
#define ROW_BYTES 2752       // MM*4
#define NODE_BYTES 16512     // KK*ROW_BYTES
#define STAGES 6             // per-CTA; multiple of NGROUPS
#define NBLK 296             // 148 SMs x 2 CTAs (one wave)
#define NGROUPS 2
#define NCONS_G 192          // consumers per group (6 warps, 172 active)
#define NPROD_WARPS 2        // one producer warp per group
#define CONS_BASE (NPROD_WARPS * 32)          // 64
#define NTH (CONS_BASE + NGROUPS * NCONS_G)   // 448
#define MAXNPB 224           // ceil(65536/296)=222, padded

#define OFF_MBAR 0                         // 6 stages * (full,empty) * 8B = 96 -> pad 128
#define OFF_CNT 128
#define OFF_BUF (OFF_CNT + MAXNPB * 4)     // 1024 (16B aligned)
#define SMEM_BYTES (OFF_BUF + STAGES * NODE_BYTES)  // 100096 -> 2 CTAs/SM

extern __shared__ char smem[];

__device__ __forceinline__ uint32_t s2u(const void* p) {
    return (uint32_t)__cvta_generic_to_shared(p);
}

__device__ __forceinline__ void mbar_init(uint32_t mbar, uint32_t count) {
    asm volatile("mbarrier.init.shared.b64 [%0], %1;" :: "r"(mbar), "r"(count) : "memory");
}

__device__ __forceinline__ void mbar_expect_tx(uint32_t mbar, uint32_t bytes) {
    asm volatile("mbarrier.arrive.expect_tx.shared.b64 _, [%0], %1;"
                 :: "r"(mbar), "r"(bytes) : "memory");
}

__device__ __forceinline__ void mbar_arrive(uint32_t mbar) {
    asm volatile("mbarrier.arrive.shared.b64 _, [%0];" :: "r"(mbar) : "memory");
}

__device__ __forceinline__ void mbar_wait(uint32_t mbar, uint32_t parity) {
    asm volatile(
        "{\n\t"
        ".reg .pred P;\n\t"
        "WAIT_%=:\n\t"
        "mbarrier.try_wait.parity.acquire.cta.shared::cta.b64 P, [%0], %1, 0x989680;\n\t"
        "@!P bra WAIT_%=;\n\t"
        "}"
        :: "r"(mbar), "r"(parity) : "memory");
}

__device__ __forceinline__ void bulk_copy(uint32_t dst_smem, const void* src_gmem,
                                          uint32_t bytes, uint32_t mbar) {
    asm volatile(
        "cp.async.bulk.shared::cluster.global.mbarrier::complete_tx::bytes "
        "[%0], [%1], %2, [%3];"
        :: "r"(dst_smem), "l"(src_gmem), "r"(bytes), "r"(mbar) : "memory");
}

__device__ __forceinline__ void bulk_store(void* dst_gmem, uint32_t src_smem,
                                           uint32_t bytes) {
    asm volatile(
        "cp.async.bulk.global.shared::cta.bulk_group [%0], [%1], %2;"
        :: "l"(dst_gmem), "r"(src_smem), "r"(bytes) : "memory");
}

__global__ void __launch_bounds__(NTH, 2)
mlp_msg_agg_pipe(
    const char*  __restrict__ msgs,    // [N,K,M] f32 as bytes
    const int*   __restrict__ counts,  // [N]
    const float* __restrict__ ts,      // [N]
    const float* __restrict__ W1, const float* __restrict__ b1,
    const float* __restrict__ W2, const float* __restrict__ b2,
    const float* __restrict__ W3, const float* __restrict__ b3,
    float*       __restrict__ out,     // [N, MM]
    float*       __restrict__ out_ts)  // [N] or null
{
    const int tid = threadIdx.x;
    const int blk = blockIdx.x;
    const int start = (int)(((long long)blk * NN) / NBLK);
    const int end   = (int)(((long long)(blk + 1) * NN) / NBLK);
    const int nnode = end - start;

    int* s_cnt = (int*)(smem + OFF_CNT);
    const uint32_t mb = s2u(smem + OFF_MBAR);   // full(s)=mb+s*16, empty(s)=mb+s*16+8
    char* buf = smem + OFF_BUF;

    // Prologue: stage counts in smem, pass timestamps through
    for (int i = tid; i < nnode; i += NTH) {
        s_cnt[i] = counts[start + i];
        if (out_ts != nullptr) out_ts[start + i] = ts[start + i];
    }
    if (tid == 0) {
        #pragma unroll
        for (int s = 0; s < STAGES; s++) {
            mbar_init(mb + s * 16, 1);    // full: 1 expect_tx arrival
            mbar_init(mb + s * 16 + 8, 1);// empty: 1 arrival (elected storer)
        }
    }
    __syncthreads();

    if (tid < CONS_BASE) {
        // ------------- producers: 2 warps, 1 active thread each -------------
        // Producer p fills group p's nodes (i ≡ p mod 2), stages {p,p+2,p+4}
        // it alone owns. Fills strictly sequential per stage -> parity safe.
        const int p = tid / 32;
        if ((tid & 31) == 0) {
            int s = p;
            int j = 0;
            for (int i = p; i < nnode; i += NGROUPS) {
                int c = s_cnt[i];
                c = (c < 0) ? 0 : ((c > KK) ? KK : c);
                const uint32_t pp = (j & 1) ^ 1;          // first pass free
                mbar_wait(mb + s * 16 + 8, pp);           // wait stage empty
                const uint32_t bytes = (uint32_t)c * ROW_BYTES;
                mbar_expect_tx(mb + s * 16, bytes);
                if (bytes) {
                    const uint32_t dst =
                        s2u(buf + s * NODE_BYTES + (KK - c) * ROW_BYTES);
                    const char* src =
                        msgs + ((size_t)(start + i) * KK + (KK - c)) * ROW_BYTES;
                    bulk_copy(dst, src, bytes, mb + s * 16);
                }
                s += NGROUPS;
                if (s >= STAGES) { s -= STAGES; j++; }
            }
        }
        return;
    }

    // ---------------- consumers: 2 independent groups ----------------
    // Node i -> stage i % 6, group i % 2; fixed stage ownership -> parity safe.
    // Output path: results are written into row 0 of the (now dead) stage
    // buffer (each thread overwrites ONLY its own 16B column, which only it
    // reads -> thread-local WAR), then one elected thread TMA-bulk-stores the
    // 2752B row to gmem, waits for the smem READ side, and releases the stage.
    const int g    = (tid - CONS_BASE) / NCONS_G;
    const int ctid = (tid - CONS_BASE) - g * NCONS_G;   // 0..191; active if < MQ
    const int bar_id = 1 + g;                            // named barrier per group

    float w1[KK * 3];
    #pragma unroll
    for (int i = 0; i < KK * 3; i++) w1[i] = __ldg(W1 + i);
    const float bb1_0 = __ldg(b1 + 0), bb1_1 = __ldg(b1 + 1), bb1_2 = __ldg(b1 + 2);
    const float w2_00 = __ldg(W2 + 0), w2_01 = __ldg(W2 + 1);
    const float w2_10 = __ldg(W2 + 2), w2_11 = __ldg(W2 + 3);
    const float w2_20 = __ldg(W2 + 4), w2_21 = __ldg(W2 + 5);
    const float bb2_0 = __ldg(b2 + 0), bb2_1 = __ldg(b2 + 1);
    const float w3_0  = __ldg(W3 + 0), w3_1  = __ldg(W3 + 1);
    const float bb3   = __ldg(b3 + 0);

    int s = g;
    int j = 0;
    for (int i = g; i < nnode; i += NGROUPS) {
        mbar_wait(mb + s * 16, (uint32_t)(j & 1));   // wait stage full (acquire)

        char* const sbuf = buf + s * NODE_BYTES;

        if (ctid < MQ) {
            int c = s_cnt[i];
            int k0 = KK - c;
            if (k0 < 0) k0 = 0;
            if (k0 > KK) k0 = KK;

            const char* nb = sbuf + ctid * 16;

            float h[4][3];
            #pragma unroll
            for (int l = 0; l < 4; l++) {
                h[l][0] = bb1_0; h[l][1] = bb1_1; h[l][2] = bb1_2;
            }

            #pragma unroll
            for (int k = 0; k < KK; k++) {
                if (k >= k0) {
                    const float4 v = *(const float4*)(nb + k * ROW_BYTES);
                    const float a  = w1[k * 3 + 0];
                    const float bW = w1[k * 3 + 1];
                    const float cW = w1[k * 3 + 2];
                    const float x[4] = {v.x, v.y, v.z, v.w};
                    #pragma unroll
                    for (int l = 0; l < 4; l++) {
                        h[l][0] = fmaf(x[l], a,  h[l][0]);
                        h[l][1] = fmaf(x[l], bW, h[l][1]);
                        h[l][2] = fmaf(x[l], cW, h[l][2]);
                    }
                }
            }

            float res[4];
            #pragma unroll
            for (int l = 0; l < 4; l++) {
                const float a0 = fmaxf(h[l][0], 0.0f);
                const float a1 = fmaxf(h[l][1], 0.0f);
                const float a2 = fmaxf(h[l][2], 0.0f);
                float g0 = bb2_0, g1 = bb2_1;
                g0 = fmaf(a0, w2_00, g0); g1 = fmaf(a0, w2_01, g1);
                g0 = fmaf(a1, w2_10, g0); g1 = fmaf(a1, w2_11, g1);
                g0 = fmaf(a2, w2_20, g0); g1 = fmaf(a2, w2_21, g1);
                g0 = fmaxf(g0, 0.0f);
                g1 = fmaxf(g1, 0.0f);
                res[l] = fmaf(g0, w3_0, fmaf(g1, w3_1, bb3));
            }

            // write result into dead row 0 of the stage buffer (own column only)
            float4 o;
            o.x = res[0]; o.y = res[1]; o.z = res[2]; o.w = res[3];
            *(float4*)(sbuf + ctid * 16) = o;
        }

        // group barrier: all results staged before the bulk store reads smem
        asm volatile("bar.sync %0, %1;" :: "r"(bar_id), "r"(NCONS_G) : "memory");

        if (ctid == 0) {
            asm volatile("fence.proxy.async.shared::cta;" ::: "memory");
            bulk_store(out + (size_t)(start + i) * MM, s2u(sbuf), ROW_BYTES);
            asm volatile("cp.async.bulk.commit_group;" ::: "memory");
            // wait only for the smem READ side, then recycle the stage
            asm volatile("cp.async.bulk.wait_group.read 0;" ::: "memory");
            mbar_arrive(mb + s * 16 + 8);   // release stage to producer
        }

        s += NGROUPS;
        if (s >= STAGES) { s -= STAGES; j++; }
    }
}

extern "C" void kernel_launch(void* const* d_in, const int* in_sizes, int n_in,
                              void* d_out, int out_size)
{
    const char*  msgs   = (const char*) d_in[0];
    const int*   counts = (const int*)  d_in[1];
    const float* ts     = (const float*)d_in[2];
    const float* W1     = (const float*)d_in[3];
    const float* b1     = (const float*)d_in[4];
    const float* W2     = (const float*)d_in[5];
    const float* b2     = (const float*)d_in[6];
    const float* W3     = (const float*)d_in[7];
    const float* b3     = (const float*)d_in[8];

    float* out = (float*)d_out;
    const int write_ts = (out_size >= NN * MM + NN) ? 1 : 0;
    float* out_ts = write_ts ? (out + (size_t)NN * MM) : nullptr;

    cudaFuncSetAttribute(mlp_msg_agg_pipe,
                         cudaFuncAttributeMaxDynamicSharedMemorySize, SMEM_BYTES);

    mlp_msg_agg_pipe<<<NBLK, NTH, SMEM_BYTES>>>(
        msgs, counts, ts, W1, b1, W2, b2, W3, b3,
        out, out_ts);
}

// round 15
// speedup vs baseline: 1.0224x; 1.0159x over previous
#include <cuda_runtime.h>
#include <cstdint>

#define NN 65536
#define KK 6
#define MM 688
#define MQ 172               // float4 per row
#define ROW_BYTES 2752       // MM*4
#define NODE_BYTES 16512     // KK*ROW_BYTES
#define STAGES 6             // per-CTA; multiple of NGROUPS
#define NBLK 296             // 148 SMs x 2 CTAs (one wave)
#define NGROUPS 2
#define NCONS_G 192          // consumers per group (6 warps, 172 active)
#define NPROD_WARPS 2        // one producer warp per group
#define CONS_BASE (NPROD_WARPS * 32)          // 64
#define NTH (CONS_BASE + NGROUPS * NCONS_G)   // 448
#define MAXNPB 224           // ceil(65536/296)=222, padded

#define OFF_MBAR 0                         // 6 stages * (full,empty) * 8B = 96 -> pad 128
#define OFF_CNT 128
#define OFF_BUF (OFF_CNT + MAXNPB * 4)     // 1024 (16B aligned)
#define SMEM_BYTES (OFF_BUF + STAGES * NODE_BYTES)  // 100096 -> 2 CTAs/SM

extern __shared__ char smem[];

__device__ __forceinline__ uint32_t s2u(const void* p) {
    return (uint32_t)__cvta_generic_to_shared(p);
}

__device__ __forceinline__ void mbar_init(uint32_t mbar, uint32_t count) {
    asm volatile("mbarrier.init.shared.b64 [%0], %1;" :: "r"(mbar), "r"(count) : "memory");
}

__device__ __forceinline__ void mbar_expect_tx(uint32_t mbar, uint32_t bytes) {
    asm volatile("mbarrier.arrive.expect_tx.shared.b64 _, [%0], %1;"
                 :: "r"(mbar), "r"(bytes) : "memory");
}

__device__ __forceinline__ void mbar_arrive(uint32_t mbar) {
    asm volatile("mbarrier.arrive.shared.b64 _, [%0];" :: "r"(mbar) : "memory");
}

__device__ __forceinline__ void mbar_wait(uint32_t mbar, uint32_t parity) {
    asm volatile(
        "{\n\t"
        ".reg .pred P;\n\t"
        "WAIT_%=:\n\t"
        "mbarrier.try_wait.parity.acquire.cta.shared::cta.b64 P, [%0], %1, 0x989680;\n\t"
        "@!P bra WAIT_%=;\n\t"
        "}"
        :: "r"(mbar), "r"(parity) : "memory");
}

__device__ __forceinline__ void bulk_copy(uint32_t dst_smem, const void* src_gmem,
                                          uint32_t bytes, uint32_t mbar) {
    asm volatile(
        "cp.async.bulk.shared::cluster.global.mbarrier::complete_tx::bytes "
        "[%0], [%1], %2, [%3];"
        :: "r"(dst_smem), "l"(src_gmem), "r"(bytes), "r"(mbar) : "memory");
}

__global__ void __launch_bounds__(NTH, 2)
mlp_msg_agg_pipe(
    const char*  __restrict__ msgs,    // [N,K,M] f32 as bytes
    const int*   __restrict__ counts,  // [N]
    const float* __restrict__ ts,      // [N]
    const float* __restrict__ W1, const float* __restrict__ b1,
    const float* __restrict__ W2, const float* __restrict__ b2,
    const float* __restrict__ W3, const float* __restrict__ b3,
    float4*      __restrict__ out,     // [N, MQ]
    float*       __restrict__ out_ts)  // [N] or null
{
    const int tid = threadIdx.x;
    const int blk = blockIdx.x;
    const int start = (int)(((long long)blk * NN) / NBLK);
    const int end   = (int)(((long long)(blk + 1) * NN) / NBLK);
    const int nnode = end - start;

    int* s_cnt = (int*)(smem + OFF_CNT);
    const uint32_t mb = s2u(smem + OFF_MBAR);   // full(s)=mb+s*16, empty(s)=mb+s*16+8
    char* buf = smem + OFF_BUF;

    // Prologue: stage counts in smem, pass timestamps through
    for (int i = tid; i < nnode; i += NTH) {
        s_cnt[i] = counts[start + i];
        if (out_ts != nullptr) out_ts[start + i] = ts[start + i];
    }
    if (tid == 0) {
        #pragma unroll
        for (int s = 0; s < STAGES; s++) {
            mbar_init(mb + s * 16, 1);            // full: 1 expect_tx arrival
            mbar_init(mb + s * 16 + 8, NCONS_G);  // empty: owning group arrives
        }
    }
    __syncthreads();

    if (tid < CONS_BASE) {
        // ------------- producers: 2 warps, 1 active thread each -------------
        // Producer p (lane 0 of warp p) fills exactly group p's nodes
        // (i ≡ p mod 2) whose stages {p, p+2, p+4} it alone owns. Fills of
        // each stage stay strictly sequential by one thread -> parity safe.
        const int p = tid / 32;
        if ((tid & 31) == 0) {
            int s = p;   // stage of node i (cycles p, p+2, p+4)
            int j = 0;   // fill index = i / STAGES
            for (int i = p; i < nnode; i += NGROUPS) {
                int c = s_cnt[i];
                c = (c < 0) ? 0 : ((c > KK) ? KK : c);
                const uint32_t pp = (j & 1) ^ 1;          // first pass free
                mbar_wait(mb + s * 16 + 8, pp);           // wait stage empty
                const uint32_t bytes = (uint32_t)c * ROW_BYTES;
                mbar_expect_tx(mb + s * 16, bytes);
                if (bytes) {
                    const uint32_t dst =
                        s2u(buf + s * NODE_BYTES + (KK - c) * ROW_BYTES);
                    const char* src =
                        msgs + ((size_t)(start + i) * KK + (KK - c)) * ROW_BYTES;
                    bulk_copy(dst, src, bytes, mb + s * 16);
                }
                s += NGROUPS;
                if (s >= STAGES) { s -= STAGES; j++; }
            }
        }
        return;
    }

    // ---------------- consumers: 2 independent groups ----------------
    // Node i -> stage i % 6, group i % 2. 6 % 2 == 0 ⇒ every stage has a
    // fixed owning group; successive fills consumed sequentially by the same
    // threads ⇒ phase-parity protocol safe.
    const int g    = (tid - CONS_BASE) / NCONS_G;
    const int ctid = (tid - CONS_BASE) - g * NCONS_G;   // 0..191; active if < MQ

    float w1[KK * 3];
    #pragma unroll
    for (int i = 0; i < KK * 3; i++) w1[i] = __ldg(W1 + i);
    const float bb1_0 = __ldg(b1 + 0), bb1_1 = __ldg(b1 + 1), bb1_2 = __ldg(b1 + 2);
    const float w2_00 = __ldg(W2 + 0), w2_01 = __ldg(W2 + 1);
    const float w2_10 = __ldg(W2 + 2), w2_11 = __ldg(W2 + 3);
    const float w2_20 = __ldg(W2 + 4), w2_21 = __ldg(W2 + 5);
    const float bb2_0 = __ldg(b2 + 0), bb2_1 = __ldg(b2 + 1);
    const float w3_0  = __ldg(W3 + 0), w3_1  = __ldg(W3 + 1);
    const float bb3   = __ldg(b3 + 0);

    int s = g;   // stage of node i (cycles g, g+2, g+4)
    int j = 0;   // fill index = i / STAGES
    for (int i = g; i < nnode; i += NGROUPS) {
        mbar_wait(mb + s * 16, (uint32_t)(j & 1));   // wait stage full (acquire)

        if (ctid < MQ) {
            int c = s_cnt[i];
            int k0 = KK - c;
            if (k0 < 0) k0 = 0;
            if (k0 > KK) k0 = KK;

            const char* nb = buf + s * NODE_BYTES + ctid * 16;

            float h[4][3];
            #pragma unroll
            for (int l = 0; l < 4; l++) {
                h[l][0] = bb1_0; h[l][1] = bb1_1; h[l][2] = bb1_2;
            }

            #pragma unroll
            for (int k = 0; k < KK; k++) {
                if (k >= k0) {
                    const float4 v = *(const float4*)(nb + k * ROW_BYTES);
                    const float a  = w1[k * 3 + 0];
                    const float bW = w1[k * 3 + 1];
                    const float cW = w1[k * 3 + 2];
                    const float x[4] = {v.x, v.y, v.z, v.w};
                    #pragma unroll
                    for (int l = 0; l < 4; l++) {
                        h[l][0] = fmaf(x[l], a,  h[l][0]);
                        h[l][1] = fmaf(x[l], bW, h[l][1]);
                        h[l][2] = fmaf(x[l], cW, h[l][2]);
                    }
                }
            }

            float res[4];
            #pragma unroll
            for (int l = 0; l < 4; l++) {
                const float a0 = fmaxf(h[l][0], 0.0f);
                const float a1 = fmaxf(h[l][1], 0.0f);
                const float a2 = fmaxf(h[l][2], 0.0f);
                float g0 = bb2_0, g1 = bb2_1;
                g0 = fmaf(a0, w2_00, g0); g1 = fmaf(a0, w2_01, g1);
                g0 = fmaf(a1, w2_10, g0); g1 = fmaf(a1, w2_11, g1);
                g0 = fmaf(a2, w2_20, g0); g1 = fmaf(a2, w2_21, g1);
                g0 = fmaxf(g0, 0.0f);
                g1 = fmaxf(g1, 0.0f);
                res[l] = fmaf(g0, w3_0, fmaf(g1, w3_1, bb3));
            }

            float4 o;
            o.x = res[0]; o.y = res[1]; o.z = res[2]; o.w = res[3];
            out[(size_t)(start + i) * MQ + ctid] = o;
        }

        mbar_arrive(mb + s * 16 + 8);           // release stage to producer

        s += NGROUPS;
        if (s >= STAGES) { s -= STAGES; j++; }
    }
}

extern "C" void kernel_launch(void* const* d_in, const int* in_sizes, int n_in,
                              void* d_out, int out_size)
{
    const char*  msgs   = (const char*) d_in[0];
    const int*   counts = (const int*)  d_in[1];
    const float* ts     = (const float*)d_in[2];
    const float* W1     = (const float*)d_in[3];
    const float* b1     = (const float*)d_in[4];
    const float* W2     = (const float*)d_in[5];
    const float* b2     = (const float*)d_in[6];
    const float* W3     = (const float*)d_in[7];
    const float* b3     = (const float*)d_in[8];

    float* out = (float*)d_out;
    const int write_ts = (out_size >= NN * MM + NN) ? 1 : 0;
    float* out_ts = write_ts ? (out + (size_t)NN * MM) : nullptr;

    cudaFuncSetAttribute(mlp_msg_agg_pipe,
                         cudaFuncAttributeMaxDynamicSharedMemorySize, SMEM_BYTES);

    mlp_msg_agg_pipe<<<NBLK, NTH, SMEM_BYTES>>>(
        msgs, counts, ts, W1, b1, W2, b2, W3, b3,
        (float4*)out, out_ts);
}

// round 16
// speedup vs baseline: 1.0307x; 1.0081x over previous
#include <cuda_runtime.h>
#include <cstdint>

#define NN 65536
#define KK 6
#define MM 688
#define MQ 172               // float4 per row
#define ROW_BYTES 2752       // MM*4
#define NODE_BYTES 16512     // KK*ROW_BYTES
#define STAGES 6             // per-CTA; multiple of NGROUPS
#define NBLK 296             // 148 SMs x 2 CTAs (one wave)
#define NGROUPS 2
#define NCONS_G 192          // consumers per group (6 warps, 172 active)
#define NPROD_WARPS 2        // one producer warp per group
#define CONS_BASE (NPROD_WARPS * 32)          // 64
#define NTH (CONS_BASE + NGROUPS * NCONS_G)   // 448
#define CHUNK 8
#define NCHUNKS (NN / CHUNK)                  // 8192

#define OFF_MBAR 0                            // 6*(full,empty)*8B = 96
#define OFF_INFO 96                           // 6 * 4B info words = 24 -> 120
#define OFF_BUF 128
#define SMEM_BYTES (OFF_BUF + STAGES * NODE_BYTES)  // 99200 -> 2 CTAs/SM

#define POISON 0xFFFFFFFFu

__device__ unsigned int g_next;   // chunk counter (reset each launch)

extern __shared__ char smem[];

__device__ __forceinline__ uint32_t s2u(const void* p) {
    return (uint32_t)__cvta_generic_to_shared(p);
}

__device__ __forceinline__ void mbar_init(uint32_t mbar, uint32_t count) {
    asm volatile("mbarrier.init.shared.b64 [%0], %1;" :: "r"(mbar), "r"(count) : "memory");
}

__device__ __forceinline__ void mbar_expect_tx(uint32_t mbar, uint32_t bytes) {
    asm volatile("mbarrier.arrive.expect_tx.shared.b64 _, [%0], %1;"
                 :: "r"(mbar), "r"(bytes) : "memory");
}

__device__ __forceinline__ void mbar_arrive(uint32_t mbar) {
    asm volatile("mbarrier.arrive.shared.b64 _, [%0];" :: "r"(mbar) : "memory");
}

__device__ __forceinline__ void mbar_wait(uint32_t mbar, uint32_t parity) {
    asm volatile(
        "{\n\t"
        ".reg .pred P;\n\t"
        "WAIT_%=:\n\t"
        "mbarrier.try_wait.parity.acquire.cta.shared::cta.b64 P, [%0], %1, 0x989680;\n\t"
        "@!P bra WAIT_%=;\n\t"
        "}"
        :: "r"(mbar), "r"(parity) : "memory");
}

__device__ __forceinline__ void bulk_copy(uint32_t dst_smem, const void* src_gmem,
                                          uint32_t bytes, uint32_t mbar) {
    asm volatile(
        "cp.async.bulk.shared::cluster.global.mbarrier::complete_tx::bytes "
        "[%0], [%1], %2, [%3];"
        :: "r"(dst_smem), "l"(src_gmem), "r"(bytes), "r"(mbar) : "memory");
}

__global__ void reset_counter_kernel() {
    if (threadIdx.x == 0) g_next = 0u;
}

__global__ void __launch_bounds__(NTH, 2)
mlp_msg_agg_pipe(
    const char*  __restrict__ msgs,    // [N,K,M] f32 as bytes
    const int*   __restrict__ counts,  // [N]
    const float* __restrict__ ts,      // [N]
    const float* __restrict__ W1, const float* __restrict__ b1,
    const float* __restrict__ W2, const float* __restrict__ b2,
    const float* __restrict__ W3, const float* __restrict__ b3,
    float4*      __restrict__ out,     // [N, MQ]
    float*       __restrict__ out_ts)  // [N] or null
{
    const int tid = threadIdx.x;
    const int blk = blockIdx.x;

    volatile unsigned int* s_info = (volatile unsigned int*)(smem + OFF_INFO);
    const uint32_t mb = s2u(smem + OFF_MBAR);   // full(s)=mb+s*16, empty(s)=mb+s*16+8
    char* buf = smem + OFF_BUF;

    // Prologue: timestamps passthrough over a static range + barrier init
    {
        const int start = (int)(((long long)blk * NN) / NBLK);
        const int end   = (int)(((long long)(blk + 1) * NN) / NBLK);
        if (out_ts != nullptr) {
            for (int i = start + tid; i < end; i += NTH) out_ts[i] = ts[i];
        }
    }
    if (tid == 0) {
        #pragma unroll
        for (int s = 0; s < STAGES; s++) {
            mbar_init(mb + s * 16, 1);            // full: 1 expect_tx arrival
            mbar_init(mb + s * 16 + 8, NCONS_G);  // empty: owning group arrives
        }
    }
    __syncthreads();

    if (tid < CONS_BASE) {
        // ------------- producers: 2 warps, 1 active thread each -------------
        // Producer p owns stages {p, p+2, p+4} (cycle of 3, j++ per wrap).
        // Dynamic: grabs 8-node chunks from the global counter, publishes
        // (node<<3)|count per stage via s_info (ordered by the release-arrive
        // of expect_tx), then a POISON fill terminates its consumer group.
        const int p = tid / 32;
        if ((tid & 31) == 0) {
            int s = p;
            int j = 0;
            for (;;) {
                const unsigned int chunk = atomicAdd(&g_next, 1u);
                if (chunk >= NCHUNKS) break;
                const int base = (int)chunk * CHUNK;
                const int4 ca = __ldg((const int4*)(counts + base));
                const int4 cb = __ldg((const int4*)(counts + base) + 1);
                int cs[CHUNK] = {ca.x, ca.y, ca.z, ca.w, cb.x, cb.y, cb.z, cb.w};
                #pragma unroll
                for (int u = 0; u < CHUNK; u++) {
                    int c = cs[u];
                    c = (c < 0) ? 0 : ((c > KK) ? KK : c);
                    const int n = base + u;
                    const uint32_t pp = (j & 1) ^ 1;     // first pass free
                    mbar_wait(mb + s * 16 + 8, pp);      // wait stage empty
                    s_info[s] = ((unsigned)n << 3) | (unsigned)c;
                    const uint32_t bytes = (uint32_t)c * ROW_BYTES;
                    mbar_expect_tx(mb + s * 16, bytes);  // release-arrive
                    if (bytes) {
                        const uint32_t dst =
                            s2u(buf + s * NODE_BYTES + (KK - c) * ROW_BYTES);
                        const char* src =
                            msgs + ((size_t)n * KK + (KK - c)) * ROW_BYTES;
                        bulk_copy(dst, src, bytes, mb + s * 16);
                    }
                    s += NGROUPS;
                    if (s >= STAGES) { s -= STAGES; j++; }
                }
            }
            // poison the next stage in sequence: consumer stops there
            mbar_wait(mb + s * 16 + 8, (uint32_t)((j & 1) ^ 1));
            s_info[s] = POISON;
            mbar_arrive(mb + s * 16);                    // release-arrive, no tx
        }
        return;
    }

    // ---------------- consumers: 2 independent groups ----------------
    // Group g follows producer g's stage sequence {g, g+2, g+4}; node id and
    // count arrive via s_info after the acquire full-wait.
    const int g    = (tid - CONS_BASE) / NCONS_G;
    const int ctid = (tid - CONS_BASE) - g * NCONS_G;   // 0..191; active if < MQ

    float w1[KK * 3];
    #pragma unroll
    for (int i = 0; i < KK * 3; i++) w1[i] = __ldg(W1 + i);
    const float bb1_0 = __ldg(b1 + 0), bb1_1 = __ldg(b1 + 1), bb1_2 = __ldg(b1 + 2);
    const float w2_00 = __ldg(W2 + 0), w2_01 = __ldg(W2 + 1);
    const float w2_10 = __ldg(W2 + 2), w2_11 = __ldg(W2 + 3);
    const float w2_20 = __ldg(W2 + 4), w2_21 = __ldg(W2 + 5);
    const float bb2_0 = __ldg(b2 + 0), bb2_1 = __ldg(b2 + 1);
    const float w3_0  = __ldg(W3 + 0), w3_1  = __ldg(W3 + 1);
    const float bb3   = __ldg(b3 + 0);

    int s = g;
    int j = 0;
    for (;;) {
        mbar_wait(mb + s * 16, (uint32_t)(j & 1));   // wait stage full (acquire)

        const unsigned int info = s_info[s];
        if (info == POISON) break;

        if (ctid < MQ) {
            const int c  = (int)(info & 7u);
            const int n  = (int)(info >> 3);
            int k0 = KK - c;

            const char* nb = buf + s * NODE_BYTES + ctid * 16;

            float h[4][3];
            #pragma unroll
            for (int l = 0; l < 4; l++) {
                h[l][0] = bb1_0; h[l][1] = bb1_1; h[l][2] = bb1_2;
            }

            #pragma unroll
            for (int k = 0; k < KK; k++) {
                if (k >= k0) {
                    const float4 v = *(const float4*)(nb + k * ROW_BYTES);
                    const float a  = w1[k * 3 + 0];
                    const float bW = w1[k * 3 + 1];
                    const float cW = w1[k * 3 + 2];
                    const float x[4] = {v.x, v.y, v.z, v.w};
                    #pragma unroll
                    for (int l = 0; l < 4; l++) {
                        h[l][0] = fmaf(x[l], a,  h[l][0]);
                        h[l][1] = fmaf(x[l], bW, h[l][1]);
                        h[l][2] = fmaf(x[l], cW, h[l][2]);
                    }
                }
            }

            float res[4];
            #pragma unroll
            for (int l = 0; l < 4; l++) {
                const float a0 = fmaxf(h[l][0], 0.0f);
                const float a1 = fmaxf(h[l][1], 0.0f);
                const float a2 = fmaxf(h[l][2], 0.0f);
                float g0 = bb2_0, g1 = bb2_1;
                g0 = fmaf(a0, w2_00, g0); g1 = fmaf(a0, w2_01, g1);
                g0 = fmaf(a1, w2_10, g0); g1 = fmaf(a1, w2_11, g1);
                g0 = fmaf(a2, w2_20, g0); g1 = fmaf(a2, w2_21, g1);
                g0 = fmaxf(g0, 0.0f);
                g1 = fmaxf(g1, 0.0f);
                res[l] = fmaf(g0, w3_0, fmaf(g1, w3_1, bb3));
            }

            float4 o;
            o.x = res[0]; o.y = res[1]; o.z = res[2]; o.w = res[3];
            out[(size_t)n * MQ + ctid] = o;
        }

        mbar_arrive(mb + s * 16 + 8);           // release stage to producer

        s += NGROUPS;
        if (s >= STAGES) { s -= STAGES; j++; }
    }
}

extern "C" void kernel_launch(void* const* d_in, const int* in_sizes, int n_in,
                              void* d_out, int out_size)
{
    const char*  msgs   = (const char*) d_in[0];
    const int*   counts = (const int*)  d_in[1];
    const float* ts     = (const float*)d_in[2];
    const float* W1     = (const float*)d_in[3];
    const float* b1     = (const float*)d_in[4];
    const float* W2     = (const float*)d_in[5];
    const float* b2     = (const float*)d_in[6];
    const float* W3     = (const float*)d_in[7];
    const float* b3     = (const float*)d_in[8];

    float* out = (float*)d_out;
    const int write_ts = (out_size >= NN * MM + NN) ? 1 : 0;
    float* out_ts = write_ts ? (out + (size_t)NN * MM) : nullptr;

    cudaFuncSetAttribute(mlp_msg_agg_pipe,
                         cudaFuncAttributeMaxDynamicSharedMemorySize, SMEM_BYTES);

    reset_counter_kernel<<<1, 32>>>();
    mlp_msg_agg_pipe<<<NBLK, NTH, SMEM_BYTES>>>(
        msgs, counts, ts, W1, b1, W2, b2, W3, b3,
        (float4*)out, out_ts);
}

// round 17
// speedup vs baseline: 1.0383x; 1.0074x over previous
#include <cuda_runtime.h>
#include <cstdint>

#define NN 65536
#define KK 6
#define MM 688
#define MQ 172               // float4 per row
#define ROW_BYTES 2752       // MM*4
#define NODE_BYTES 16512     // KK*ROW_BYTES
#define STAGES 6             // per-CTA; multiple of NGROUPS
#define NBLK 296             // 148 SMs x 2 CTAs (one wave)
#define NGROUPS 2
#define NCONS_G 192          // consumers per group (6 warps, 172 active)
#define NPROD_WARPS 2        // one producer warp per group
#define CONS_BASE (NPROD_WARPS * 32)          // 64
#define NTH (CONS_BASE + NGROUPS * NCONS_G)   // 448
#define CHUNK 8
#define NCHUNKS (NN / CHUNK)                  // 8192
#define NPROD_TOTAL (NBLK * NPROD_WARPS)      // 592

#define OFF_MBAR 0                            // 6*(full,empty)*8B = 96
#define OFF_INFO 96                           // 6 * 4B info words
#define OFF_BUF 128
#define SMEM_BYTES (OFF_BUF + STAGES * NODE_BYTES)  // 99200 -> 2 CTAs/SM

#define POISON 0xFFFFFFFFu

__device__ unsigned int g_next;   // chunk counter (zero-init; self-reset at end)
__device__ unsigned int g_done;   // producer completion counter (ditto)

extern __shared__ char smem[];

__device__ __forceinline__ uint32_t s2u(const void* p) {
    return (uint32_t)__cvta_generic_to_shared(p);
}

__device__ __forceinline__ void mbar_init(uint32_t mbar, uint32_t count) {
    asm volatile("mbarrier.init.shared.b64 [%0], %1;" :: "r"(mbar), "r"(count) : "memory");
}

__device__ __forceinline__ void mbar_expect_tx(uint32_t mbar, uint32_t bytes) {
    asm volatile("mbarrier.arrive.expect_tx.shared.b64 _, [%0], %1;"
                 :: "r"(mbar), "r"(bytes) : "memory");
}

__device__ __forceinline__ void mbar_arrive(uint32_t mbar) {
    asm volatile("mbarrier.arrive.shared.b64 _, [%0];" :: "r"(mbar) : "memory");
}

__device__ __forceinline__ void mbar_wait(uint32_t mbar, uint32_t parity) {
    asm volatile(
        "{\n\t"
        ".reg .pred P;\n\t"
        "WAIT_%=:\n\t"
        "mbarrier.try_wait.parity.acquire.cta.shared::cta.b64 P, [%0], %1, 0x989680;\n\t"
        "@!P bra WAIT_%=;\n\t"
        "}"
        :: "r"(mbar), "r"(parity) : "memory");
}

__device__ __forceinline__ void bulk_copy(uint32_t dst_smem, const void* src_gmem,
                                          uint32_t bytes, uint32_t mbar) {
    asm volatile(
        "cp.async.bulk.shared::cluster.global.mbarrier::complete_tx::bytes "
        "[%0], [%1], %2, [%3];"
        :: "r"(dst_smem), "l"(src_gmem), "r"(bytes), "r"(mbar) : "memory");
}

__global__ void __launch_bounds__(NTH, 2)
mlp_msg_agg_pipe(
    const char*  __restrict__ msgs,    // [N,K,M] f32 as bytes
    const int*   __restrict__ counts,  // [N]
    const float* __restrict__ ts,      // [N]
    const float* __restrict__ W1, const float* __restrict__ b1,
    const float* __restrict__ W2, const float* __restrict__ b2,
    const float* __restrict__ W3, const float* __restrict__ b3,
    float4*      __restrict__ out,     // [N, MQ]
    float*       __restrict__ out_ts)  // [N] or null
{
    const int tid = threadIdx.x;
    const int blk = blockIdx.x;

    volatile unsigned int* s_info = (volatile unsigned int*)(smem + OFF_INFO);
    const uint32_t mb = s2u(smem + OFF_MBAR);   // full(s)=mb+s*16, empty(s)=mb+s*16+8
    char* buf = smem + OFF_BUF;

    // Prologue: timestamps passthrough over a static range + barrier init
    {
        const int start = (int)(((long long)blk * NN) / NBLK);
        const int end   = (int)(((long long)(blk + 1) * NN) / NBLK);
        if (out_ts != nullptr) {
            for (int i = start + tid; i < end; i += NTH) out_ts[i] = ts[i];
        }
    }
    if (tid == 0) {
        #pragma unroll
        for (int s = 0; s < STAGES; s++) {
            mbar_init(mb + s * 16, 1);            // full: 1 expect_tx arrival
            mbar_init(mb + s * 16 + 8, NCONS_G);  // empty: owning group arrives
        }
    }
    __syncthreads();

    if (tid < CONS_BASE) {
        // ------------- producers: 2 warps, 1 active thread each -------------
        // Producer p owns stages {p, p+2, p+4}. Dynamic: grabs 8-node chunks
        // from the global counter, publishes (node<<3)|count per stage via
        // s_info (ordered by the release-arrive of expect_tx); POISON fill
        // terminates its consumer group.
        const int p = tid / 32;
        if ((tid & 31) == 0) {
            int s = p;
            int j = 0;
            for (;;) {
                const unsigned int chunk = atomicAdd(&g_next, 1u);
                if (chunk >= NCHUNKS) break;
                const int base = (int)chunk * CHUNK;
                const int4 ca = __ldg((const int4*)(counts + base));
                const int4 cb = __ldg((const int4*)(counts + base) + 1);
                int cs[CHUNK] = {ca.x, ca.y, ca.z, ca.w, cb.x, cb.y, cb.z, cb.w};
                #pragma unroll
                for (int u = 0; u < CHUNK; u++) {
                    int c = cs[u];
                    c = (c < 0) ? 0 : ((c > KK) ? KK : c);
                    const int n = base + u;
                    const uint32_t pp = (j & 1) ^ 1;     // first pass free
                    mbar_wait(mb + s * 16 + 8, pp);      // wait stage empty
                    s_info[s] = ((unsigned)n << 3) | (unsigned)c;
                    const uint32_t bytes = (uint32_t)c * ROW_BYTES;
                    mbar_expect_tx(mb + s * 16, bytes);  // release-arrive
                    if (bytes) {
                        const uint32_t dst =
                            s2u(buf + s * NODE_BYTES + (KK - c) * ROW_BYTES);
                        const char* src =
                            msgs + ((size_t)n * KK + (KK - c)) * ROW_BYTES;
                        bulk_copy(dst, src, bytes, mb + s * 16);
                    }
                    s += NGROUPS;
                    if (s >= STAGES) { s -= STAGES; j++; }
                }
            }
            // poison the next stage in sequence: consumer stops there
            mbar_wait(mb + s * 16 + 8, (uint32_t)((j & 1) ^ 1));
            s_info[s] = POISON;
            mbar_arrive(mb + s * 16);                    // release-arrive, no tx

            // self-cleaning counter reset: each producer arrives here only
            // AFTER its final atomicAdd on g_next, so when the last producer
            // sees g_done == NPROD_TOTAL-1, all g_next traffic has ceased and
            // the reset races with nothing. Restores zero-state for the next
            // graph replay -- no separate reset launch needed.
            __threadfence();
            const unsigned int d = atomicAdd(&g_done, 1u);
            if (d == (unsigned)(NPROD_TOTAL - 1)) {
                g_next = 0u;
                __threadfence();
                g_done = 0u;
            }
        }
        return;
    }

    // ---------------- consumers: 2 independent groups ----------------
    // Group g follows producer g's stage sequence {g, g+2, g+4}; node id and
    // count arrive via s_info after the acquire full-wait.
    const int g    = (tid - CONS_BASE) / NCONS_G;
    const int ctid = (tid - CONS_BASE) - g * NCONS_G;   // 0..191; active if < MQ

    float w1[KK * 3];
    #pragma unroll
    for (int i = 0; i < KK * 3; i++) w1[i] = __ldg(W1 + i);
    const float bb1_0 = __ldg(b1 + 0), bb1_1 = __ldg(b1 + 1), bb1_2 = __ldg(b1 + 2);
    const float w2_00 = __ldg(W2 + 0), w2_01 = __ldg(W2 + 1);
    const float w2_10 = __ldg(W2 + 2), w2_11 = __ldg(W2 + 3);
    const float w2_20 = __ldg(W2 + 4), w2_21 = __ldg(W2 + 5);
    const float bb2_0 = __ldg(b2 + 0), bb2_1 = __ldg(b2 + 1);
    const float w3_0  = __ldg(W3 + 0), w3_1  = __ldg(W3 + 1);
    const float bb3   = __ldg(b3 + 0);

    int s = g;
    int j = 0;
    for (;;) {
        mbar_wait(mb + s * 16, (uint32_t)(j & 1));   // wait stage full (acquire)

        const unsigned int info = s_info[s];
        if (info == POISON) break;

        if (ctid < MQ) {
            const int c  = (int)(info & 7u);
            const int n  = (int)(info >> 3);
            int k0 = KK - c;

            const char* nb = buf + s * NODE_BYTES + ctid * 16;

            float h[4][3];
            #pragma unroll
            for (int l = 0; l < 4; l++) {
                h[l][0] = bb1_0; h[l][1] = bb1_1; h[l][2] = bb1_2;
            }

            #pragma unroll
            for (int k = 0; k < KK; k++) {
                if (k >= k0) {
                    const float4 v = *(const float4*)(nb + k * ROW_BYTES);
                    const float a  = w1[k * 3 + 0];
                    const float bW = w1[k * 3 + 1];
                    const float cW = w1[k * 3 + 2];
                    const float x[4] = {v.x, v.y, v.z, v.w};
                    #pragma unroll
                    for (int l = 0; l < 4; l++) {
                        h[l][0] = fmaf(x[l], a,  h[l][0]);
                        h[l][1] = fmaf(x[l], bW, h[l][1]);
                        h[l][2] = fmaf(x[l], cW, h[l][2]);
                    }
                }
            }

            float res[4];
            #pragma unroll
            for (int l = 0; l < 4; l++) {
                const float a0 = fmaxf(h[l][0], 0.0f);
                const float a1 = fmaxf(h[l][1], 0.0f);
                const float a2 = fmaxf(h[l][2], 0.0f);
                float g0 = bb2_0, g1 = bb2_1;
                g0 = fmaf(a0, w2_00, g0); g1 = fmaf(a0, w2_01, g1);
                g0 = fmaf(a1, w2_10, g0); g1 = fmaf(a1, w2_11, g1);
                g0 = fmaf(a2, w2_20, g0); g1 = fmaf(a2, w2_21, g1);
                g0 = fmaxf(g0, 0.0f);
                g1 = fmaxf(g1, 0.0f);
                res[l] = fmaf(g0, w3_0, fmaf(g1, w3_1, bb3));
            }

            float4 o;
            o.x = res[0]; o.y = res[1]; o.z = res[2]; o.w = res[3];
            out[(size_t)n * MQ + ctid] = o;
        }

        mbar_arrive(mb + s * 16 + 8);           // release stage to producer

        s += NGROUPS;
        if (s >= STAGES) { s -= STAGES; j++; }
    }
}

extern "C" void kernel_launch(void* const* d_in, const int* in_sizes, int n_in,
                              void* d_out, int out_size)
{
    const char*  msgs   = (const char*) d_in[0];
    const int*   counts = (const int*)  d_in[1];
    const float* ts     = (const float*)d_in[2];
    const float* W1     = (const float*)d_in[3];
    const float* b1     = (const float*)d_in[4];
    const float* W2     = (const float*)d_in[5];
    const float* b2     = (const float*)d_in[6];
    const float* W3     = (const float*)d_in[7];
    const float* b3     = (const float*)d_in[8];

    float* out = (float*)d_out;
    const int write_ts = (out_size >= NN * MM + NN) ? 1 : 0;
    float* out_ts = write_ts ? (out + (size_t)NN * MM) : nullptr;

    cudaFuncSetAttribute(mlp_msg_agg_pipe,
                         cudaFuncAttributeMaxDynamicSharedMemorySize, SMEM_BYTES);

    mlp_msg_agg_pipe<<<NBLK, NTH, SMEM_BYTES>>>(
        msgs, counts, ts, W1, b1, W2, b2, W3, b3,
        (float4*)out, out_ts);
}